// round 1
// baseline (speedup 1.0000x reference)
#include <cuda_runtime.h>

// Problem constants
#define BB 8
#define OC 6
#define LL 3600
#define DEVN 5
#define HOUT 60
#define NTILES 18000   // (BB*OC*DEVN) groups * (3600/48) tiles = 240*75

#define NTHREADS 256
#define TM 48          // rows per tile
#define NP 96          // padded hidden width (90 -> 96)
#define AS 98          // activation row stride in floats (even -> 8B aligned rows, bank-skewed)

typedef unsigned long long u64;

__device__ __forceinline__ u64 pack2(float x, float y) {
    u64 r; asm("mov.b64 %0, {%1, %2};" : "=l"(r) : "f"(x), "f"(y)); return r;
}
__device__ __forceinline__ void unpack2(u64 v, float& x, float& y) {
    asm("mov.b64 {%0, %1}, %2;" : "=f"(x), "=f"(y) : "l"(v));
}
__device__ __forceinline__ u64 ffma2(u64 a, u64 b, u64 c) {
    u64 d; asm("fma.rn.f32x2 %0, %1, %2, %3;" : "=l"(d) : "l"(a), "l"(b), "l"(c)); return d;
}

// 48x96 = (48x90) @ (90x96-padded) GEMM + bias + relu, all operands in SMEM.
// Thread grid 16x16: each thread owns 3 rows x 3 column-pairs (f32x2 accums).
__device__ __forceinline__ void gemm90(const float* __restrict__ Ain,
                                       const float* __restrict__ Ws,
                                       const float* __restrict__ biasp,
                                       float* __restrict__ Bout, int tid) {
    const int ty = tid >> 4;          // 0..15
    const int tx = tid & 15;          // 0..15
    const int r0 = ty * 3;            // rows r0..r0+2
    const int c0 = tx * 6;            // cols c0..c0+5 (3 pairs)

    u64 acc[3][3];
#pragma unroll
    for (int q = 0; q < 3; q++) {
        u64 bp = *(const u64*)(biasp + c0 + 2 * q);
        acc[0][q] = bp; acc[1][q] = bp; acc[2][q] = bp;
    }

    const float* ap = Ain + r0 * AS;
    const float* wp = Ws + c0;
#pragma unroll 6
    for (int k = 0; k < 90; k++) {
        u64 a0 = pack2(ap[k], ap[k]);
        u64 a1 = pack2(ap[AS + k], ap[AS + k]);
        u64 a2 = pack2(ap[2 * AS + k], ap[2 * AS + k]);
        const float* wk = wp + k * NP;
        u64 w0 = *(const u64*)(wk);
        u64 w1 = *(const u64*)(wk + 2);
        u64 w2 = *(const u64*)(wk + 4);
        acc[0][0] = ffma2(a0, w0, acc[0][0]);
        acc[0][1] = ffma2(a0, w1, acc[0][1]);
        acc[0][2] = ffma2(a0, w2, acc[0][2]);
        acc[1][0] = ffma2(a1, w0, acc[1][0]);
        acc[1][1] = ffma2(a1, w1, acc[1][1]);
        acc[1][2] = ffma2(a1, w2, acc[1][2]);
        acc[2][0] = ffma2(a2, w0, acc[2][0]);
        acc[2][1] = ffma2(a2, w1, acc[2][1]);
        acc[2][2] = ffma2(a2, w2, acc[2][2]);
    }

#pragma unroll
    for (int i = 0; i < 3; i++) {
#pragma unroll
        for (int q = 0; q < 3; q++) {
            float lo, hi; unpack2(acc[i][q], lo, hi);
            float2 v = make_float2(fmaxf(lo, 0.f), fmaxf(hi, 0.f));
            *(float2*)(Bout + (r0 + i) * AS + c0 + 2 * q) = v;
        }
    }
}

// SMEM layout (floats):
//  W1s: 90*96   W2s: 90*96   W0s: 7*96   Abuf: 48*98  Bbuf: 48*98
//  b0p,b1p,b2p,W3s: 96 each  ctrls: 64  Xv: 48*5
#define SMEM_FLOATS (90*NP*2 + 7*NP + TM*AS*2 + NP*4 + 64 + TM*5)
#define SMEM_BYTES  (SMEM_FLOATS * 4)

__global__ void __launch_bounds__(NTHREADS, 1)
mlp_fused_kernel(const float* __restrict__ x, const float* __restrict__ ac,
                 const float* __restrict__ W0, const float* __restrict__ b0,
                 const float* __restrict__ W1, const float* __restrict__ b1,
                 const float* __restrict__ W2, const float* __restrict__ b2,
                 const float* __restrict__ W3, const float* __restrict__ b3,
                 float* __restrict__ out) {
    extern __shared__ float sm[];
    float* W1s  = sm;
    float* W2s  = W1s + 90 * NP;
    float* W0s  = W2s + 90 * NP;
    float* Abuf = W0s + 7 * NP;
    float* Bbuf = Abuf + TM * AS;
    float* b0p  = Bbuf + TM * AS;
    float* b1p  = b0p + NP;
    float* b2p  = b1p + NP;
    float* W3s  = b2p + NP;
    float* ctrls = W3s + NP;
    float* Xv   = ctrls + 64;

    const int tid = threadIdx.x;

    // ---- stage all weights into SMEM once (persistent CTA) ----
    for (int idx = tid; idx < 90 * NP; idx += NTHREADS) {
        int r = idx / NP, c = idx - r * NP;
        float v1 = (c < 90) ? W1[r * 90 + c] : 0.f;
        float v2 = (c < 90) ? W2[r * 90 + c] : 0.f;
        W1s[idx] = v1;
        W2s[idx] = v2;
    }
    for (int idx = tid; idx < 7 * NP; idx += NTHREADS) {
        int r = idx / NP, c = idx - r * NP;
        W0s[idx] = (c < 90) ? W0[r * 90 + c] : 0.f;
    }
    if (tid < NP) {
        b0p[tid] = (tid < 90) ? b0[tid] : 0.f;
        b1p[tid] = (tid < 90) ? b1[tid] : 0.f;
        b2p[tid] = (tid < 90) ? b2[tid] : 0.f;
        W3s[tid] = (tid < 90) ? W3[tid] : 0.f;
    }
    if (tid < 64) ctrls[tid] = (tid < 60) ? ac[tid] : 0.f;
    const float b3v = b3[0];
    __syncthreads();

    // ---- persistent tile loop ----
    for (int tile = blockIdx.x; tile < NTILES; tile += gridDim.x) {
        int g = tile / 75, t = tile - g * 75;          // group, l-tile
        int b = g / 30, rem = g - b * 30;
        int oc = rem / 5, dev = rem - oc * 5;
        int l0 = t * TM;

        float c0v = ctrls[(oc * 5 + dev) * 2 + 0];
        float c1v = ctrls[(oc * 5 + dev) * 2 + 1];

        __syncthreads();   // protect Abuf/Xv from previous iteration's readers

        // stage 5 x-values per row
        for (int idx = tid; idx < TM * 5; idx += NTHREADS) {
            int r = idx / 5, m = idx - r * 5;
            int l = l0 + r;
            int i = l / 60, j = l - i * 60;
            Xv[idx] = x[(b * 64 + (i + dev)) * 64 + (j + m)];
        }
        __syncthreads();

        // layer 1: 7 -> 90 (electrode order: [x1,x2,x3,x4,c0,x0,c1])
        for (int idx = tid; idx < TM * NP; idx += NTHREADS) {
            int r = idx / NP, c = idx - r * NP;
            const float* xr = Xv + r * 5;
            float v = b0p[c];
            v = fmaf(W0s[0 * NP + c], xr[1], v);
            v = fmaf(W0s[1 * NP + c], xr[2], v);
            v = fmaf(W0s[2 * NP + c], xr[3], v);
            v = fmaf(W0s[3 * NP + c], xr[4], v);
            v = fmaf(W0s[4 * NP + c], c0v, v);
            v = fmaf(W0s[5 * NP + c], xr[0], v);
            v = fmaf(W0s[6 * NP + c], c1v, v);
            Abuf[r * AS + c] = fmaxf(v, 0.f);
        }
        __syncthreads();

        // layer 2 and layer 3: 90 -> 90 GEMMs
        gemm90(Abuf, W1s, b1p, Bbuf, tid);
        __syncthreads();
        gemm90(Bbuf, W2s, b2p, Abuf, tid);
        __syncthreads();

        // layer 4: 90 -> 1, accumulate over dev into out via atomics
        if (tid < 192) {
            int r = tid >> 2, q = tid & 3;
            const float* arow = Abuf + r * AS;
            float s = 0.f;
            for (int j = q; j < 90; j += 4) s = fmaf(arow[j], W3s[j], s);
            s += __shfl_xor_sync(0xffffffffu, s, 1);
            s += __shfl_xor_sync(0xffffffffu, s, 2);
            if (q == 0) {
                atomicAdd(&out[(b * OC + oc) * LL + l0 + r], s + b3v);
            }
        }
    }
}

__global__ void zero_kernel(float* o, int n) {
    int i = blockIdx.x * blockDim.x + threadIdx.x;
    if (i < n) o[i] = 0.f;
}

extern "C" void kernel_launch(void* const* d_in, const int* in_sizes, int n_in,
                              void* d_out, int out_size) {
    const float* x  = (const float*)d_in[0];
    const float* ac = (const float*)d_in[1];
    const float* W0 = (const float*)d_in[2];
    const float* b0 = (const float*)d_in[3];
    const float* W1 = (const float*)d_in[4];
    const float* b1 = (const float*)d_in[5];
    const float* W2 = (const float*)d_in[6];
    const float* b2 = (const float*)d_in[7];
    const float* W3 = (const float*)d_in[8];
    const float* b3 = (const float*)d_in[9];
    float* out = (float*)d_out;

    int sms = 0;
    cudaDeviceGetAttribute(&sms, cudaDevAttrMultiProcessorCount, 0);
    if (sms <= 0) sms = 148;
    cudaFuncSetAttribute(mlp_fused_kernel,
                         cudaFuncAttributeMaxDynamicSharedMemorySize, SMEM_BYTES);

    zero_kernel<<<(BB * OC * LL + 255) / 256, 256>>>(out, BB * OC * LL);
    mlp_fused_kernel<<<sms, NTHREADS, SMEM_BYTES>>>(x, ac, W0, b0, W1, b1, W2, b2,
                                                    W3, b3, out);
}

// round 3
// speedup vs baseline: 2.2528x; 2.2528x over previous
#include <cuda_runtime.h>
#include <cstdint>

// ---------------- problem constants ----------------
#define BB 8
#define OC 6
#define LL 3600
#define NROWS 864000
#define TM 128
#define NTILES (NROWS / TM)     // 6750
#define NT 512

// ---------------- SMEM layout (bytes) ----------------
// Weight frag buffers: [kt(12)][n(96)][tig(4)] float2 -> 36864 B each
// Act frag buffer:     [kt(12)][m(128)][tig(4)] float2 -> 49152 B
#define SM_W1F  0
#define SM_W2F  36864
#define SM_ACT  73728
#define SM_W0   122880          // 7 x 96 fp32 row-major
#define SM_B0P  125568
#define SM_B1P  125952
#define SM_B2P  126336
#define SM_W3   126720
#define SM_CTRL 127104
#define SM_XV   127360          // 128 rows x 8 floats
#define SM_PSUM 131456          // 4 x 128 floats
#define SMEM_BYTES 133504

__device__ __forceinline__ uint32_t to_tf32(float x) {
    uint32_t u; asm("cvt.rna.tf32.f32 %0, %1;" : "=r"(u) : "f"(x)); return u;
}

__device__ __forceinline__ void mma_tf32(float c[4], const uint32_t a[4],
                                         uint32_t b0, uint32_t b1) {
    asm volatile(
        "mma.sync.aligned.m16n8k8.row.col.f32.tf32.tf32.f32 "
        "{%0,%1,%2,%3}, {%4,%5,%6,%7}, {%8,%9}, {%0,%1,%2,%3};"
        : "+f"(c[0]), "+f"(c[1]), "+f"(c[2]), "+f"(c[3])
        : "r"(a[0]), "r"(a[1]), "r"(a[2]), "r"(a[3]), "r"(b0), "r"(b1));
}

// act frag float index for element (row m, col k)
__device__ __forceinline__ int act_fidx(int k, int m) {
    return (((k >> 3) * 128 + m) * 8) + ((k & 3) * 2) + ((k >> 2) & 1);
}

__global__ void __launch_bounds__(NT, 1)
mlp_hmma_kernel(const float* __restrict__ x, const float* __restrict__ ac,
                const float* __restrict__ W0, const float* __restrict__ b0,
                const float* __restrict__ W1, const float* __restrict__ b1,
                const float* __restrict__ W2, const float* __restrict__ b2,
                const float* __restrict__ W3, const float* __restrict__ b3,
                float* __restrict__ out) {
    extern __shared__ char smc[];
    float2* w1f = (float2*)(smc + SM_W1F);
    float2* w2f = (float2*)(smc + SM_W2F);
    float2* actf = (float2*)(smc + SM_ACT);
    float*  actS = (float*)(smc + SM_ACT);
    float*  w0s  = (float*)(smc + SM_W0);
    float*  b0p  = (float*)(smc + SM_B0P);
    float*  b1p  = (float*)(smc + SM_B1P);
    float*  b2p  = (float*)(smc + SM_B2P);
    float*  w3s  = (float*)(smc + SM_W3);
    float*  ctrl = (float*)(smc + SM_CTRL);
    float*  xv   = (float*)(smc + SM_XV);
    float*  psum = (float*)(smc + SM_PSUM);

    const int tid = threadIdx.x;
    const int w   = tid >> 5;
    const int wy  = w >> 2;          // 0..3 : row slice (32 rows)
    const int wx  = w & 3;           // 0..3 : col slice (24 cols)
    const int lane = tid & 31;
    const int gid  = lane >> 2;      // 0..7
    const int tig  = lane & 3;       // 0..3

    // ---- stage weights into fragment layout (tf32-rounded) ----
    for (int i = tid; i < 4608; i += NT) {
        int kt = i / 384, rem = i - kt * 384;
        int n = rem >> 2, tg = rem & 3;
        int k0 = kt * 8 + tg, k1 = k0 + 4;
        float2 v1, v2;
        v1.x = (k0 < 90 && n < 90) ? W1[k0 * 90 + n] : 0.f;
        v1.y = (k1 < 90 && n < 90) ? W1[k1 * 90 + n] : 0.f;
        v2.x = (k0 < 90 && n < 90) ? W2[k0 * 90 + n] : 0.f;
        v2.y = (k1 < 90 && n < 90) ? W2[k1 * 90 + n] : 0.f;
        v1.x = __uint_as_float(to_tf32(v1.x)); v1.y = __uint_as_float(to_tf32(v1.y));
        v2.x = __uint_as_float(to_tf32(v2.x)); v2.y = __uint_as_float(to_tf32(v2.y));
        w1f[i] = v1; w2f[i] = v2;
    }
    for (int i = tid; i < 7 * 96; i += NT) {
        int e = i / 96, c = i - e * 96;
        w0s[i] = (c < 90) ? W0[e * 90 + c] : 0.f;
    }
    if (tid < 96) {
        b0p[tid] = (tid < 90) ? b0[tid] : 0.f;
        b1p[tid] = (tid < 90) ? b1[tid] : 0.f;
        b2p[tid] = (tid < 90) ? b2[tid] : 0.f;
        w3s[tid] = (tid < 90) ? W3[tid] : 0.f;
    }
    if (tid < 64) ctrl[tid] = (tid < 60) ? ac[tid] : 0.f;
    const float b3v = b3[0];
    __syncthreads();

    for (int tile = blockIdx.x; tile < NTILES; tile += gridDim.x) {
        const int t0 = tile * TM;

        // ---- stage per-row electrode vectors ----
        if (tid < TM) {
            int r = t0 + tid;
            int g = r / LL, l = r - g * LL;
            int b = g / 30, rem = g - b * 30;
            int oc = rem / 5, dev = rem - oc * 5;
            int i = l / 60, j = l - i * 60;
            const float* xr = x + (b * 64 + (i + dev)) * 64 + j;
            float* v = xv + tid * 8;
            float x0 = xr[0], x1 = xr[1], x2 = xr[2], x3 = xr[3], x4 = xr[4];
            const float* ct = ctrl + (oc * 5 + dev) * 2;
            v[0] = x1; v[1] = x2; v[2] = x3; v[3] = x4;
            v[4] = ct[0]; v[5] = x0; v[6] = ct[1]; v[7] = 0.f;
        }
        __syncthreads();

        // ---- layer 1: 7 -> 96, write act frag (tf32) ----
        for (int it = tid; it < TM * 24; it += NT) {
            int m = it / 24, cc = (it - m * 24) * 4;
            const float* v = xv + m * 8;
            const float* wc = w0s + cc;
            float4 a = *(const float4*)(b0p + cc);
#pragma unroll
            for (int e = 0; e < 7; e++) {
                float xe = v[e];
                float4 ww = *(const float4*)(wc + e * 96);
                a.x = fmaf(ww.x, xe, a.x); a.y = fmaf(ww.y, xe, a.y);
                a.z = fmaf(ww.z, xe, a.z); a.w = fmaf(ww.w, xe, a.w);
            }
            int kt = cc >> 3, comp = (cc >> 2) & 1;
            int base = (kt * 128 + m) * 8 + comp;
            actS[base + 0] = __uint_as_float(to_tf32(fmaxf(a.x, 0.f)));
            actS[base + 2] = __uint_as_float(to_tf32(fmaxf(a.y, 0.f)));
            actS[base + 4] = __uint_as_float(to_tf32(fmaxf(a.z, 0.f)));
            actS[base + 6] = __uint_as_float(to_tf32(fmaxf(a.w, 0.f)));
        }
        __syncthreads();

        // ---- layer 2 GEMM: D1 = act @ W1 ----
        float c1[2][3][4];
#pragma unroll
        for (int mt = 0; mt < 2; mt++)
#pragma unroll
            for (int nt = 0; nt < 3; nt++)
#pragma unroll
                for (int q = 0; q < 4; q++) c1[mt][nt][q] = 0.f;

#pragma unroll
        for (int kt = 0; kt < 12; kt++) {
            uint32_t afr[2][4];
#pragma unroll
            for (int mt = 0; mt < 2; mt++) {
                int slot = (kt * 128 + wy * 32 + mt * 16 + gid) * 4 + tig;
                float2 lo = actf[slot];
                float2 hi = actf[slot + 32];
                afr[mt][0] = __float_as_uint(lo.x);
                afr[mt][1] = __float_as_uint(hi.x);
                afr[mt][2] = __float_as_uint(lo.y);
                afr[mt][3] = __float_as_uint(hi.y);
            }
#pragma unroll
            for (int nt = 0; nt < 3; nt++) {
                float2 bf = w1f[(kt * 96 + wx * 24 + nt * 8 + gid) * 4 + tig];
                uint32_t bb0 = __float_as_uint(bf.x), bb1 = __float_as_uint(bf.y);
                mma_tf32(c1[0][nt], afr[0], bb0, bb1);
                mma_tf32(c1[1][nt], afr[1], bb0, bb1);
            }
        }
        __syncthreads();   // all warps done reading act -> safe to overwrite

        // ---- epilogue 1: bias + relu + tf32, write act frag ----
#pragma unroll
        for (int mt = 0; mt < 2; mt++) {
            int r0 = wy * 32 + mt * 16 + gid;
#pragma unroll
            for (int nt = 0; nt < 3; nt++) {
                int n0 = wx * 24 + nt * 8 + tig * 2;
                float bn0 = b1p[n0], bn1 = b1p[n0 + 1];
                actS[act_fidx(n0,     r0)]     = __uint_as_float(to_tf32(fmaxf(c1[mt][nt][0] + bn0, 0.f)));
                actS[act_fidx(n0 + 1, r0)]     = __uint_as_float(to_tf32(fmaxf(c1[mt][nt][1] + bn1, 0.f)));
                actS[act_fidx(n0,     r0 + 8)] = __uint_as_float(to_tf32(fmaxf(c1[mt][nt][2] + bn0, 0.f)));
                actS[act_fidx(n0 + 1, r0 + 8)] = __uint_as_float(to_tf32(fmaxf(c1[mt][nt][3] + bn1, 0.f)));
            }
        }
        __syncthreads();

        // ---- layer 3 GEMM: D2 = act @ W2 ----
        float c2[2][3][4];
#pragma unroll
        for (int mt = 0; mt < 2; mt++)
#pragma unroll
            for (int nt = 0; nt < 3; nt++)
#pragma unroll
                for (int q = 0; q < 4; q++) c2[mt][nt][q] = 0.f;

#pragma unroll
        for (int kt = 0; kt < 12; kt++) {
            uint32_t afr[2][4];
#pragma unroll
            for (int mt = 0; mt < 2; mt++) {
                int slot = (kt * 128 + wy * 32 + mt * 16 + gid) * 4 + tig;
                float2 lo = actf[slot];
                float2 hi = actf[slot + 32];
                afr[mt][0] = __float_as_uint(lo.x);
                afr[mt][1] = __float_as_uint(hi.x);
                afr[mt][2] = __float_as_uint(lo.y);
                afr[mt][3] = __float_as_uint(hi.y);
            }
#pragma unroll
            for (int nt = 0; nt < 3; nt++) {
                float2 bf = w2f[(kt * 96 + wx * 24 + nt * 8 + gid) * 4 + tig];
                uint32_t bb0 = __float_as_uint(bf.x), bb1 = __float_as_uint(bf.y);
                mma_tf32(c2[0][nt], afr[0], bb0, bb1);
                mma_tf32(c2[1][nt], afr[1], bb0, bb1);
            }
        }

        // ---- epilogue 2: bias + relu + dot(W3) + warp reduce -> psum ----
#pragma unroll
        for (int mt = 0; mt < 2; mt++) {
            int r0 = wy * 32 + mt * 16 + gid;
            float s0 = 0.f, s1 = 0.f;
#pragma unroll
            for (int nt = 0; nt < 3; nt++) {
                int n0 = wx * 24 + nt * 8 + tig * 2;
                float bn0 = b1p[0]; // placeholder avoid compiler confusion
                bn0 = b2p[n0];
                float bn1 = b2p[n0 + 1];
                float w30 = w3s[n0], w31 = w3s[n0 + 1];
                s0 = fmaf(fmaxf(c2[mt][nt][0] + bn0, 0.f), w30, s0);
                s0 = fmaf(fmaxf(c2[mt][nt][1] + bn1, 0.f), w31, s0);
                s1 = fmaf(fmaxf(c2[mt][nt][2] + bn0, 0.f), w30, s1);
                s1 = fmaf(fmaxf(c2[mt][nt][3] + bn1, 0.f), w31, s1);
            }
            s0 += __shfl_xor_sync(0xffffffffu, s0, 1);
            s0 += __shfl_xor_sync(0xffffffffu, s0, 2);
            s1 += __shfl_xor_sync(0xffffffffu, s1, 1);
            s1 += __shfl_xor_sync(0xffffffffu, s1, 2);
            if (tig == 0) {
                psum[wx * 128 + r0] = s0;
                psum[wx * 128 + r0 + 8] = s1;
            }
        }
        __syncthreads();

        // ---- finalize: sum 4 col-slices, add b3, atomic into out ----
        if (tid < TM) {
            float tot = psum[tid] + psum[128 + tid] + psum[256 + tid]
                      + psum[384 + tid] + b3v;
            int r = t0 + tid;
            int g = r / LL, l = r - g * LL;
            int b = g / 30, rem = g - b * 30;
            int oc = rem / 5;
            atomicAdd(out + (b * OC + oc) * LL + l, tot);
        }
        __syncthreads();
    }
}

__global__ void zero_kernel(float* o, int n) {
    int i = blockIdx.x * blockDim.x + threadIdx.x;
    if (i < n) o[i] = 0.f;
}

extern "C" void kernel_launch(void* const* d_in, const int* in_sizes, int n_in,
                              void* d_out, int out_size) {
    const float* x  = (const float*)d_in[0];
    const float* ac = (const float*)d_in[1];
    const float* W0 = (const float*)d_in[2];
    const float* b0 = (const float*)d_in[3];
    const float* W1 = (const float*)d_in[4];
    const float* b1 = (const float*)d_in[5];
    const float* W2 = (const float*)d_in[6];
    const float* b2 = (const float*)d_in[7];
    const float* W3 = (const float*)d_in[8];
    const float* b3 = (const float*)d_in[9];
    float* out = (float*)d_out;

    int sms = 0;
    cudaDeviceGetAttribute(&sms, cudaDevAttrMultiProcessorCount, 0);
    if (sms <= 0) sms = 148;
    cudaFuncSetAttribute(mlp_hmma_kernel,
                         cudaFuncAttributeMaxDynamicSharedMemorySize, SMEM_BYTES);

    zero_kernel<<<(BB * OC * LL + 255) / 256, 256>>>(out, BB * OC * LL);
    mlp_hmma_kernel<<<sms, NT, SMEM_BYTES>>>(x, ac, W0, b0, W1, b1, W2, b2,
                                             W3, b3, out);
}

// round 4
// speedup vs baseline: 2.5408x; 1.1278x over previous
#include <cuda_runtime.h>
#include <cstdint>

// ---------------- problem constants ----------------
#define BB 8
#define OC 6
#define LL 3600
#define NROWS 864000
#define TM 128
#define NTILES (NROWS / TM)     // 6750
#define NT 512

// ---------------- SMEM layout (bytes) ----------------
// All fragment buffers use padded rows: 4 float2 payload + 1 float2 pad (40 B)
// act : [kt(12)][m(128)][tig(4)+pad]  -> 61440 B
// w1f/w2f: [kt(12)][n(96)][tig(4)+pad] -> 46080 B each
// w0f : [n(96)][tig(4)+pad]           -> 3840 B
// xh/xl: [m(128)][tig(4)+pad]         -> 5120 B each
#define SM_ACT   0
#define SM_W1F   61440
#define SM_W2F   107520
#define SM_W0F   153600
#define SM_XH    157440
#define SM_XL    162560
#define SM_B0P   167680
#define SM_B1P   168064
#define SM_B2P   168448
#define SM_W3S   168832
#define SM_CTRL  169216
#define SM_PSUM  169472
#define SMEM_BYTES 171520

__device__ __forceinline__ float tf32r(float x) {
    uint32_t u; asm("cvt.rna.tf32.f32 %0, %1;" : "=r"(u) : "f"(x));
    return __uint_as_float(u);
}

__device__ __forceinline__ void mma8(float c[4], const uint32_t a[4],
                                     uint32_t b0, uint32_t b1) {
    asm volatile(
        "mma.sync.aligned.m16n8k8.row.col.f32.tf32.tf32.f32 "
        "{%0,%1,%2,%3}, {%4,%5,%6,%7}, {%8,%9}, {%0,%1,%2,%3};"
        : "+f"(c[0]), "+f"(c[1]), "+f"(c[2]), "+f"(c[3])
        : "r"(a[0]), "r"(a[1]), "r"(a[2]), "r"(a[3]), "r"(b0), "r"(b1));
}

// 128x96 GEMM tile: warp (wy,wx) computes 32x24; A from padded act frags, B from
// padded weight frags. arow = wy*32+gid, bcol = wx*24+gid.
__device__ __forceinline__ void gemm_block(const float2* __restrict__ actp,
                                           const float2* __restrict__ wf,
                                           int arow, int bcol, int tig,
                                           float c[2][3][4]) {
#pragma unroll
    for (int mt = 0; mt < 2; mt++)
#pragma unroll
        for (int nt = 0; nt < 3; nt++)
#pragma unroll
            for (int q = 0; q < 4; q++) c[mt][nt][q] = 0.f;
#pragma unroll
    for (int kt = 0; kt < 12; kt++) {
        uint32_t afr[2][4];
#pragma unroll
        for (int mt = 0; mt < 2; mt++) {
            const float2 lo = actp[(kt * 128 + arow + mt * 16) * 5 + tig];
            const float2 hi = actp[(kt * 128 + arow + mt * 16 + 8) * 5 + tig];
            afr[mt][0] = __float_as_uint(lo.x);
            afr[mt][1] = __float_as_uint(hi.x);
            afr[mt][2] = __float_as_uint(lo.y);
            afr[mt][3] = __float_as_uint(hi.y);
        }
#pragma unroll
        for (int nt = 0; nt < 3; nt++) {
            const float2 bf = wf[(kt * 96 + bcol + nt * 8) * 5 + tig];
            const uint32_t b0 = __float_as_uint(bf.x), b1 = __float_as_uint(bf.y);
            mma8(c[0][nt], afr[0], b0, b1);
            mma8(c[1][nt], afr[1], b0, b1);
        }
    }
}

// bias + relu + tf32-round, store C back into padded act frag layout.
__device__ __forceinline__ void epi_store(float* __restrict__ actS,
                                          const float* __restrict__ bias,
                                          int wy, int wx, int gid, int tig, int oe,
                                          const float c[2][3][4]) {
#pragma unroll
    for (int mt = 0; mt < 2; mt++) {
        const int r = wy * 32 + mt * 16 + gid;
#pragma unroll
        for (int nt = 0; nt < 3; nt++) {
            const int n0 = wx * 24 + nt * 8 + tig * 2;
            const int ktc = wx * 3 + nt;
            const float bn0 = bias[n0], bn1 = bias[n0 + 1];
            float* p = actS + (ktc * 128 + r) * 10;
            p[oe]          = tf32r(fmaxf(c[mt][nt][0] + bn0, 0.f));
            p[oe + 2]      = tf32r(fmaxf(c[mt][nt][1] + bn1, 0.f));
            p[80 + oe]     = tf32r(fmaxf(c[mt][nt][2] + bn0, 0.f));
            p[80 + oe + 2] = tf32r(fmaxf(c[mt][nt][3] + bn1, 0.f));
        }
    }
}

__global__ void __launch_bounds__(NT, 1)
mlp_hmma2_kernel(const float* __restrict__ x, const float* __restrict__ ac,
                 const float* __restrict__ W0, const float* __restrict__ b0,
                 const float* __restrict__ W1, const float* __restrict__ b1,
                 const float* __restrict__ W2, const float* __restrict__ b2,
                 const float* __restrict__ W3, const float* __restrict__ b3,
                 float* __restrict__ out) {
    extern __shared__ char smc[];
    float2* actp = (float2*)(smc + SM_ACT);
    float*  actS = (float*)(smc + SM_ACT);
    float2* w1f  = (float2*)(smc + SM_W1F);
    float2* w2f  = (float2*)(smc + SM_W2F);
    float2* w0f  = (float2*)(smc + SM_W0F);
    float2* xh2  = (float2*)(smc + SM_XH);
    float2* xl2  = (float2*)(smc + SM_XL);
    float*  b0p  = (float*)(smc + SM_B0P);
    float*  b1p  = (float*)(smc + SM_B1P);
    float*  b2p  = (float*)(smc + SM_B2P);
    float*  w3s  = (float*)(smc + SM_W3S);
    float*  ctrl = (float*)(smc + SM_CTRL);
    float*  psum = (float*)(smc + SM_PSUM);

    const int tid  = threadIdx.x;
    const int w    = tid >> 5;
    const int wy   = w >> 2;
    const int wx   = w & 3;
    const int lane = tid & 31;
    const int gid  = lane >> 2;
    const int tig  = lane & 3;
    const int oe   = ((2 * tig) & 3) * 2 + (tig >> 1);
    const int arow = wy * 32 + gid;
    const int bcol = wx * 24 + gid;

    // ---- stage weights (once) ----
    for (int i = tid; i < 12 * 96 * 4; i += NT) {
        int kt = i / 384, rem = i - kt * 384;
        int n = rem >> 2, tg = rem & 3;
        int k0 = kt * 8 + tg, k1 = k0 + 4;
        float2 v1, v2;
        v1.x = (k0 < 90 && n < 90) ? tf32r(W1[k0 * 90 + n]) : 0.f;
        v1.y = (k1 < 90 && n < 90) ? tf32r(W1[k1 * 90 + n]) : 0.f;
        v2.x = (k0 < 90 && n < 90) ? tf32r(W2[k0 * 90 + n]) : 0.f;
        v2.y = (k1 < 90 && n < 90) ? tf32r(W2[k1 * 90 + n]) : 0.f;
        w1f[(kt * 96 + n) * 5 + tg] = v1;
        w2f[(kt * 96 + n) * 5 + tg] = v2;
    }
    for (int i = tid; i < 96 * 4; i += NT) {
        int n = i >> 2, tg = i & 3;
        float2 v;
        v.x = (n < 90) ? tf32r(W0[tg * 90 + n]) : 0.f;
        v.y = (tg + 4 < 7 && n < 90) ? tf32r(W0[(tg + 4) * 90 + n]) : 0.f;
        w0f[n * 5 + tg] = v;
    }
    if (tid < 96) {
        b0p[tid] = (tid < 90) ? b0[tid] : 0.f;
        b1p[tid] = (tid < 90) ? b1[tid] : 0.f;
        b2p[tid] = (tid < 90) ? b2[tid] : 0.f;
        w3s[tid] = (tid < 90) ? W3[tid] : 0.f;
    }
    if (tid < 64) ctrl[tid] = (tid < 60) ? ac[tid] : 0.f;
    const float b3v = b3[0];
    __syncthreads();

    for (int tile = blockIdx.x; tile < NTILES; tile += gridDim.x) {
        const int t0 = tile * TM;

        // ---- stage electrode vectors (hi/lo split), frag layout ----
        {
            const int m = tid >> 2, p = tid & 3;
            const int r = t0 + m;
            int g = r / LL, l = r - g * LL;
            int b = g / 30, rem = g - b * 30;
            int oc = rem / 5, dev = rem - oc * 5;
            int i = l / 60, j = l - i * 60;
            const float* xr = x + (b * 64 + (i + dev)) * 64 + j;
            float va, vb;
            if (p == 0)      { va = xr[1]; vb = ctrl[(oc * 5 + dev) * 2]; }
            else if (p == 1) { va = xr[2]; vb = xr[0]; }
            else if (p == 2) { va = xr[3]; vb = ctrl[(oc * 5 + dev) * 2 + 1]; }
            else             { va = xr[4]; vb = 0.f; }
            const float ahv = tf32r(va), bhv = tf32r(vb);
            xh2[m * 5 + p] = make_float2(ahv, bhv);
            xl2[m * 5 + p] = make_float2(tf32r(va - ahv), tf32r(vb - bhv));
        }
        __syncthreads();

        // ---- layer 1: K=8 MMA with hi/lo input split ----
        {
            float cL[2][3][4];
#pragma unroll
            for (int mt = 0; mt < 2; mt++)
#pragma unroll
                for (int nt = 0; nt < 3; nt++)
#pragma unroll
                    for (int q = 0; q < 4; q++) cL[mt][nt][q] = 0.f;

            uint32_t afh[2][4], afl[2][4];
#pragma unroll
            for (int mt = 0; mt < 2; mt++) {
                const float2 lo  = xh2[(arow + mt * 16) * 5 + tig];
                const float2 hi  = xh2[(arow + mt * 16 + 8) * 5 + tig];
                const float2 lo2 = xl2[(arow + mt * 16) * 5 + tig];
                const float2 hi2 = xl2[(arow + mt * 16 + 8) * 5 + tig];
                afh[mt][0] = __float_as_uint(lo.x);  afh[mt][1] = __float_as_uint(hi.x);
                afh[mt][2] = __float_as_uint(lo.y);  afh[mt][3] = __float_as_uint(hi.y);
                afl[mt][0] = __float_as_uint(lo2.x); afl[mt][1] = __float_as_uint(hi2.x);
                afl[mt][2] = __float_as_uint(lo2.y); afl[mt][3] = __float_as_uint(hi2.y);
            }
#pragma unroll
            for (int nt = 0; nt < 3; nt++) {
                const float2 bf = w0f[(bcol + nt * 8) * 5 + tig];
                const uint32_t bb0 = __float_as_uint(bf.x), bb1 = __float_as_uint(bf.y);
                mma8(cL[0][nt], afh[0], bb0, bb1);
                mma8(cL[1][nt], afh[1], bb0, bb1);
                mma8(cL[0][nt], afl[0], bb0, bb1);
                mma8(cL[1][nt], afl[1], bb0, bb1);
            }
            epi_store(actS, b0p, wy, wx, gid, tig, oe, cL);
        }
        __syncthreads();

        // ---- layer 2 GEMM ----
        float c1[2][3][4];
        gemm_block(actp, w1f, arow, bcol, tig, c1);
        __syncthreads();                 // all reads of act done
        epi_store(actS, b1p, wy, wx, gid, tig, oe, c1);
        __syncthreads();

        // ---- layer 3 GEMM + fused final dot ----
        float c2[2][3][4];
        gemm_block(actp, w2f, arow, bcol, tig, c2);
#pragma unroll
        for (int mt = 0; mt < 2; mt++) {
            const int r = wy * 32 + mt * 16 + gid;
            float s0 = 0.f, s1 = 0.f;
#pragma unroll
            for (int nt = 0; nt < 3; nt++) {
                const int n0 = wx * 24 + nt * 8 + tig * 2;
                const float bn0 = b2p[n0], bn1 = b2p[n0 + 1];
                const float w30 = w3s[n0], w31 = w3s[n0 + 1];
                s0 = fmaf(fmaxf(c2[mt][nt][0] + bn0, 0.f), w30, s0);
                s0 = fmaf(fmaxf(c2[mt][nt][1] + bn1, 0.f), w31, s0);
                s1 = fmaf(fmaxf(c2[mt][nt][2] + bn0, 0.f), w30, s1);
                s1 = fmaf(fmaxf(c2[mt][nt][3] + bn1, 0.f), w31, s1);
            }
            s0 += __shfl_xor_sync(0xffffffffu, s0, 1);
            s0 += __shfl_xor_sync(0xffffffffu, s0, 2);
            s1 += __shfl_xor_sync(0xffffffffu, s1, 1);
            s1 += __shfl_xor_sync(0xffffffffu, s1, 2);
            if (tig == 0) {
                psum[wx * 128 + r] = s0;
                psum[wx * 128 + r + 8] = s1;
            }
        }
        __syncthreads();

        // ---- finalize: sum 4 col-slices, add b3, atomic into out ----
        if (tid < TM) {
            float tot = psum[tid] + psum[128 + tid] + psum[256 + tid]
                      + psum[384 + tid] + b3v;
            int r = t0 + tid;
            int g = r / LL, l = r - g * LL;
            int b = g / 30, rem = g - b * 30;
            int oc = rem / 5;
            atomicAdd(out + (b * OC + oc) * LL + l, tot);
        }
        __syncthreads();
    }
}

__global__ void zero_kernel(float* o, int n) {
    int i = blockIdx.x * blockDim.x + threadIdx.x;
    if (i < n) o[i] = 0.f;
}

extern "C" void kernel_launch(void* const* d_in, const int* in_sizes, int n_in,
                              void* d_out, int out_size) {
    const float* x  = (const float*)d_in[0];
    const float* ac = (const float*)d_in[1];
    const float* W0 = (const float*)d_in[2];
    const float* b0 = (const float*)d_in[3];
    const float* W1 = (const float*)d_in[4];
    const float* b1 = (const float*)d_in[5];
    const float* W2 = (const float*)d_in[6];
    const float* b2 = (const float*)d_in[7];
    const float* W3 = (const float*)d_in[8];
    const float* b3 = (const float*)d_in[9];
    float* out = (float*)d_out;

    int sms = 0;
    cudaDeviceGetAttribute(&sms, cudaDevAttrMultiProcessorCount, 0);
    if (sms <= 0) sms = 148;
    cudaFuncSetAttribute(mlp_hmma2_kernel,
                         cudaFuncAttributeMaxDynamicSharedMemorySize, SMEM_BYTES);

    zero_kernel<<<(BB * OC * LL + 255) / 256, 256>>>(out, BB * OC * LL);
    mlp_hmma2_kernel<<<sms, NT, SMEM_BYTES>>>(x, ac, W0, b0, W1, b1, W2, b2,
                                              W3, b3, out);
}

// round 5
// speedup vs baseline: 7.2297x; 2.8454x over previous
#include <cuda_runtime.h>
#include <cuda_fp16.h>
#include <cstdint>

// ---------------- problem constants ----------------
#define BB 8
#define OC 6
#define LL 3600
#define NROWS 864000
#define TM 128
#define NTILES (NROWS / TM)     // 6750
#define NT 256

// ---------------- SMEM layout (bytes) ----------------
// act : [kt(6)][m(128)][8 half2 words, xor-swizzled]  -> 24576 B
// w1f/w2f: [kt(6)][n(96)][8 words]                    -> 18432 B each
// w0f : [n(96)][8 words]                              -> 3072 B
// xv  : [m(128)][8 words] (hi pairs even, lo odd)     -> 4096 B
#define SM_ACT  0
#define SM_W1F  24576
#define SM_W2F  43008
#define SM_W0F  61440
#define SM_XV   64512
#define SM_B0P  68608
#define SM_B1P  68992
#define SM_B2P  69376
#define SM_W3S  69760
#define SM_CTRL 70144
#define SM_PSUM 70400
#define SMEM_BYTES 71424

__device__ __forceinline__ uint32_t pack_h2(float a, float b) {
    __half2 h = __floats2half2_rn(a, b);
    return *(uint32_t*)&h;
}

__device__ __forceinline__ void mma16(float c[4], const uint32_t a[4],
                                      uint32_t b0, uint32_t b1) {
    asm volatile(
        "mma.sync.aligned.m16n8k16.row.col.f32.f16.f16.f32 "
        "{%0,%1,%2,%3}, {%4,%5,%6,%7}, {%8,%9}, {%0,%1,%2,%3};"
        : "+f"(c[0]), "+f"(c[1]), "+f"(c[2]), "+f"(c[3])
        : "r"(a[0]), "r"(a[1]), "r"(a[2]), "r"(a[3]), "r"(b0), "r"(b1));
}

// 128x96 @ 96x96 GEMM; warp tile 32 rows x 48 cols. Conflict-free LDS.64 frags.
__device__ __forceinline__ void gemm16(const uint32_t* __restrict__ actw,
                                       const uint32_t* __restrict__ wf,
                                       int arowb, int bcolb, int gid, int aoff,
                                       float c[2][6][4]) {
#pragma unroll
    for (int mt = 0; mt < 2; mt++)
#pragma unroll
        for (int nt = 0; nt < 6; nt++)
#pragma unroll
            for (int q = 0; q < 4; q++) c[mt][nt][q] = 0.f;

#pragma unroll
    for (int kt = 0; kt < 6; kt++) {
        const int abase = (kt * 128 + arowb + gid) * 8 + aoff;
        const uint2 r0 = *(const uint2*)(actw + abase);            // row gid
        const uint2 r1 = *(const uint2*)(actw + abase + 64);       // +8
        const uint2 r2 = *(const uint2*)(actw + abase + 128);      // +16
        const uint2 r3 = *(const uint2*)(actw + abase + 192);      // +24
        const uint32_t af0[4] = {r0.x, r1.x, r0.y, r1.y};
        const uint32_t af1[4] = {r2.x, r3.x, r2.y, r3.y};
        const int bbase = (kt * 96 + bcolb + gid) * 8 + aoff;
#pragma unroll
        for (int nt = 0; nt < 6; nt++) {
            const uint2 bv = *(const uint2*)(wf + bbase + nt * 64);
            mma16(c[0][nt], af0, bv.x, bv.y);
            mma16(c[1][nt], af1, bv.x, bv.y);
        }
    }
}

// bias + relu + fp16 pack, store into act frag layout.
__device__ __forceinline__ void epi_store16(uint32_t* __restrict__ actw,
                                            const float* __restrict__ bias,
                                            int arowb, int bcolb, int gid, int tig,
                                            int xorv, const float c[2][6][4]) {
#pragma unroll
    for (int mt = 0; mt < 2; mt++) {
        const int r0 = arowb + mt * 16 + gid;
#pragma unroll
        for (int nt = 0; nt < 6; nt++) {
            const int n0 = bcolb + nt * 8 + 2 * tig;
            const int ktp = (bcolb >> 4) + (nt >> 1);
            const int v = (2 * tig + (nt & 1)) ^ xorv;
            const float2 bq = *(const float2*)(bias + n0);
            actw[(ktp * 128 + r0) * 8 + v] =
                pack_h2(fmaxf(c[mt][nt][0] + bq.x, 0.f), fmaxf(c[mt][nt][1] + bq.y, 0.f));
            actw[(ktp * 128 + r0 + 8) * 8 + v] =
                pack_h2(fmaxf(c[mt][nt][2] + bq.x, 0.f), fmaxf(c[mt][nt][3] + bq.y, 0.f));
        }
    }
}

__global__ void __launch_bounds__(NT)
mlp_fp16_kernel(const float* __restrict__ x, const float* __restrict__ ac,
                const float* __restrict__ W0, const float* __restrict__ b0,
                const float* __restrict__ W1, const float* __restrict__ b1,
                const float* __restrict__ W2, const float* __restrict__ b2,
                const float* __restrict__ W3, const float* __restrict__ b3,
                float* __restrict__ out, int ntasks) {
    extern __shared__ char smc[];
    uint32_t* actw = (uint32_t*)(smc + SM_ACT);
    uint32_t* w1fw = (uint32_t*)(smc + SM_W1F);
    uint32_t* w2fw = (uint32_t*)(smc + SM_W2F);
    uint32_t* w0fw = (uint32_t*)(smc + SM_W0F);
    uint32_t* xvw  = (uint32_t*)(smc + SM_XV);
    float* b0p  = (float*)(smc + SM_B0P);
    float* b1p  = (float*)(smc + SM_B1P);
    float* b2p  = (float*)(smc + SM_B2P);
    float* w3s  = (float*)(smc + SM_W3S);
    float* ctrl = (float*)(smc + SM_CTRL);
    float* psum = (float*)(smc + SM_PSUM);

    const int tid  = threadIdx.x;
    const int w    = tid >> 5;
    const int wy   = w >> 1;
    const int wx   = w & 1;
    const int lane = tid & 31;
    const int gid  = lane >> 2;
    const int tig  = lane & 3;
    const int xorv = 2 * (gid & 3);
    const int aoff = (2 * tig) ^ xorv;
    const int arowb = wy * 32;
    const int bcolb = wx * 48;

    // ---- stage weights (once) ----
    for (int i = tid; i < 2304; i += NT) {
        int kt = i / 384, rem = i - kt * 384;
        int n = rem >> 2, t = rem & 3;
        int k0 = kt * 16 + 2 * t;
        float a1 = (k0 < 90 && n < 90) ? W1[k0 * 90 + n] : 0.f;
        float b1v = (k0 + 1 < 90 && n < 90) ? W1[(k0 + 1) * 90 + n] : 0.f;
        float c1v = (k0 + 8 < 90 && n < 90) ? W1[(k0 + 8) * 90 + n] : 0.f;
        float d1 = (k0 + 9 < 90 && n < 90) ? W1[(k0 + 9) * 90 + n] : 0.f;
        float a2 = (k0 < 90 && n < 90) ? W2[k0 * 90 + n] : 0.f;
        float b2v = (k0 + 1 < 90 && n < 90) ? W2[(k0 + 1) * 90 + n] : 0.f;
        float c2v = (k0 + 8 < 90 && n < 90) ? W2[(k0 + 8) * 90 + n] : 0.f;
        float d2 = (k0 + 9 < 90 && n < 90) ? W2[(k0 + 9) * 90 + n] : 0.f;
        int base = (kt * 96 + n) * 8;
        int va = (2 * t) ^ (2 * (n & 3));
        w1fw[base + va] = pack_h2(a1, b1v);
        w1fw[base + va + 1] = pack_h2(c1v, d1);
        w2fw[base + va] = pack_h2(a2, b2v);
        w2fw[base + va + 1] = pack_h2(c2v, d2);
    }
    for (int i = tid; i < 384; i += NT) {
        int n = i >> 2, t = i & 3;
        int e0 = 2 * t, e1 = 2 * t + 1;
        float v0 = (e0 < 7 && n < 90) ? W0[e0 * 90 + n] : 0.f;
        float v1 = (e1 < 7 && n < 90) ? W0[e1 * 90 + n] : 0.f;
        uint32_t wv = pack_h2(v0, v1);
        int base = n * 8;
        int va = (2 * t) ^ (2 * (n & 3));
        w0fw[base + va] = wv;        // hi half of k
        w0fw[base + va + 1] = wv;    // lo half duplicates W0
    }
    if (tid < 96) {
        b0p[tid] = (tid < 90) ? b0[tid] : 0.f;
        b1p[tid] = (tid < 90) ? b1[tid] : 0.f;
        b2p[tid] = (tid < 90) ? b2[tid] : 0.f;
        w3s[tid] = (tid < 90) ? W3[tid] : 0.f;
    }
    if (tid < 64) ctrl[tid] = (tid < 60) ? ac[tid] : 0.f;
    const float b3v = b3[0];
    __syncthreads();

    for (int tile = blockIdx.x; tile < ntasks; tile += gridDim.x) {
        const int t0 = tile * TM;

        // ---- stage electrode rows: fp16 hi/lo split packed into k16 ----
        if (tid < TM) {
            const int m = tid, r = t0 + m;
            int g = r / LL, l = r - g * LL;
            int b = g / 30, rem = g - b * 30;
            int oc = rem / 5, dev = rem - oc * 5;
            int i = l / 60, j = l - i * 60;
            const float* xr = x + (b * 64 + (i + dev)) * 64 + j;
            float e[8];
            e[0] = xr[1]; e[1] = xr[2]; e[2] = xr[3]; e[3] = xr[4];
            e[4] = ctrl[(oc * 5 + dev) * 2];
            e[5] = xr[0];
            e[6] = ctrl[(oc * 5 + dev) * 2 + 1];
            e[7] = 0.f;
            const int mb = m * 8, mx = 2 * (m & 3);
#pragma unroll
            for (int t = 0; t < 4; t++) {
                float ea = e[2 * t], eb = e[2 * t + 1];
                __half ha = __float2half_rn(ea), hb = __float2half_rn(eb);
                float la = ea - __half2float(ha), lb = eb - __half2float(hb);
                int idx = mb + ((2 * t) ^ mx);
                xvw[idx] = pack_h2(__half2float(ha), __half2float(hb));
                xvw[idx + 1] = pack_h2(la, lb);
            }
        }
        __syncthreads();

        // ---- layer 1: single k16 MMA per (mt,nt) with hi+lo fused ----
        {
            float cL[2][6][4];
#pragma unroll
            for (int mt = 0; mt < 2; mt++)
#pragma unroll
                for (int nt = 0; nt < 6; nt++)
#pragma unroll
                    for (int q = 0; q < 4; q++) cL[mt][nt][q] = 0.f;

            const int abase = (arowb + gid) * 8 + aoff;
            const uint2 r0 = *(const uint2*)(xvw + abase);
            const uint2 r1 = *(const uint2*)(xvw + abase + 64);
            const uint2 r2 = *(const uint2*)(xvw + abase + 128);
            const uint2 r3 = *(const uint2*)(xvw + abase + 192);
            const uint32_t af0[4] = {r0.x, r1.x, r0.y, r1.y};
            const uint32_t af1[4] = {r2.x, r3.x, r2.y, r3.y};
            const int bbase = (bcolb + gid) * 8 + aoff;
#pragma unroll
            for (int nt = 0; nt < 6; nt++) {
                const uint2 bv = *(const uint2*)(w0fw + bbase + nt * 64);
                mma16(cL[0][nt], af0, bv.x, bv.y);
                mma16(cL[1][nt], af1, bv.x, bv.y);
            }
            epi_store16(actw, b0p, arowb, bcolb, gid, tig, xorv, cL);
        }
        __syncthreads();

        // ---- layer 2 GEMM ----
        float c1[2][6][4];
        gemm16(actw, w1fw, arowb, bcolb, gid, aoff, c1);
        __syncthreads();
        epi_store16(actw, b1p, arowb, bcolb, gid, tig, xorv, c1);
        __syncthreads();

        // ---- layer 3 GEMM + fused 90->1 dot ----
        float c2[2][6][4];
        gemm16(actw, w2fw, arowb, bcolb, gid, aoff, c2);
#pragma unroll
        for (int mt = 0; mt < 2; mt++) {
            const int r0 = arowb + mt * 16 + gid;
            float s0 = 0.f, s1 = 0.f;
#pragma unroll
            for (int nt = 0; nt < 6; nt++) {
                const int n0 = bcolb + nt * 8 + 2 * tig;
                const float2 bq = *(const float2*)(b2p + n0);
                const float2 wq = *(const float2*)(w3s + n0);
                s0 = fmaf(fmaxf(c2[mt][nt][0] + bq.x, 0.f), wq.x, s0);
                s0 = fmaf(fmaxf(c2[mt][nt][1] + bq.y, 0.f), wq.y, s0);
                s1 = fmaf(fmaxf(c2[mt][nt][2] + bq.x, 0.f), wq.x, s1);
                s1 = fmaf(fmaxf(c2[mt][nt][3] + bq.y, 0.f), wq.y, s1);
            }
            s0 += __shfl_xor_sync(0xffffffffu, s0, 1);
            s0 += __shfl_xor_sync(0xffffffffu, s0, 2);
            s1 += __shfl_xor_sync(0xffffffffu, s1, 1);
            s1 += __shfl_xor_sync(0xffffffffu, s1, 2);
            if (tig == 0) {
                psum[wx * 128 + r0] = s0;
                psum[wx * 128 + r0 + 8] = s1;
            }
        }
        __syncthreads();

        // ---- finalize: sum col-halves, add b3, atomic into out ----
        if (tid < TM) {
            float tot = psum[tid] + psum[128 + tid] + b3v;
            int r = t0 + tid;
            int g = r / LL, l = r - g * LL;
            int b = g / 30, rem = g - b * 30;
            int oc = rem / 5;
            atomicAdd(out + (b * OC + oc) * LL + l, tot);
        }
        __syncthreads();
    }
}

__global__ void zero_kernel(float* o, int n) {
    int i = blockIdx.x * blockDim.x + threadIdx.x;
    if (i < n) o[i] = 0.f;
}

extern "C" void kernel_launch(void* const* d_in, const int* in_sizes, int n_in,
                              void* d_out, int out_size) {
    const float* x  = (const float*)d_in[0];
    const float* ac = (const float*)d_in[1];
    const float* W0 = (const float*)d_in[2];
    const float* b0 = (const float*)d_in[3];
    const float* W1 = (const float*)d_in[4];
    const float* b1 = (const float*)d_in[5];
    const float* W2 = (const float*)d_in[6];
    const float* b2 = (const float*)d_in[7];
    const float* W3 = (const float*)d_in[8];
    const float* b3 = (const float*)d_in[9];
    float* out = (float*)d_out;

    int sms = 0;
    cudaDeviceGetAttribute(&sms, cudaDevAttrMultiProcessorCount, 0);
    if (sms <= 0) sms = 148;
    cudaFuncSetAttribute(mlp_fp16_kernel,
                         cudaFuncAttributeMaxDynamicSharedMemorySize, SMEM_BYTES);
    int occ = 1;
    cudaOccupancyMaxActiveBlocksPerMultiprocessor(&occ, mlp_fp16_kernel, NT,
                                                  SMEM_BYTES);
    if (occ < 1) occ = 1;
    int grid = occ * sms;
    if (grid > NTILES) grid = NTILES;

    zero_kernel<<<(BB * OC * LL + 255) / 256, 256>>>(out, BB * OC * LL);
    mlp_fp16_kernel<<<grid, NT, SMEM_BYTES>>>(x, ac, W0, b0, W1, b1, W2, b2,
                                              W3, b3, out, NTILES);
}

// round 6
// speedup vs baseline: 8.8573x; 1.2251x over previous
#include <cuda_runtime.h>
#include <cuda_fp16.h>
#include <cstdint>

// ---------------- problem constants ----------------
#define OC 6
#define LL 3600
#define NROWS 864000
#define NT 128
#define CTILE 128                 // 4 warps x 32 rows
#define NCTILES (NROWS / CTILE)   // 6750

__device__ __forceinline__ uint32_t pack_h2(float a, float b) {
    __half2 h = __floats2half2_rn(a, b);
    return *(uint32_t*)&h;
}

__device__ __forceinline__ void mma16(float c[4], const uint32_t a[4],
                                      uint32_t b0, uint32_t b1) {
    asm volatile(
        "mma.sync.aligned.m16n8k16.row.col.f32.f16.f16.f32 "
        "{%0,%1,%2,%3}, {%4,%5,%6,%7}, {%8,%9}, {%0,%1,%2,%3};"
        : "+f"(c[0]), "+f"(c[1]), "+f"(c[2]), "+f"(c[3])
        : "r"(a[0]), "r"(a[1]), "r"(a[2]), "r"(a[3]), "r"(b0), "r"(b1));
}

// B-frag SMEM layout: word idx = ((kt*6+ntp)*8+gid)*16 + tig*4 + q
//   q0 = b0 of nt=2ntp, q1 = b1 of nt=2ntp, q2 = b0 of nt=2ntp+1, q3 = b1.
// Thread's 4 words contiguous -> one LDS.128, 4 conflict-free wavefronts.
struct SMem {
    uint32_t w1f[4608];
    uint32_t w2f[4608];
    float2 b0f[48], b1f[48], b2f[48], w3f[48];
    float cs[64];
};

// 96-wide GEMM over 6 K-blocks: C[2][12][4] += A @ W (W from SMEM frags).
__device__ __forceinline__ void gemmw(const uint32_t* __restrict__ wf,
                                      const uint32_t af[2][6][4],
                                      float c[2][12][4], int gid, int tig) {
#pragma unroll
    for (int kt = 0; kt < 6; kt++) {
#pragma unroll
        for (int ntp = 0; ntp < 6; ntp++) {
            const uint4 bv =
                *(const uint4*)(wf + ((kt * 6 + ntp) * 8 + gid) * 16 + tig * 4);
            mma16(c[0][2 * ntp],     af[0][kt], bv.x, bv.y);
            mma16(c[1][2 * ntp],     af[1][kt], bv.x, bv.y);
            mma16(c[0][2 * ntp + 1], af[0][kt], bv.z, bv.w);
            mma16(c[1][2 * ntp + 1], af[1][kt], bv.z, bv.w);
        }
    }
}

// relu + fp16-pack C fragments into next layer's A fragments (in registers).
__device__ __forceinline__ void c_to_a(const float c[2][12][4],
                                       uint32_t af[2][6][4]) {
#pragma unroll
    for (int mt = 0; mt < 2; mt++)
#pragma unroll
        for (int kt = 0; kt < 6; kt++) {
            af[mt][kt][0] = pack_h2(fmaxf(c[mt][2 * kt][0], 0.f),
                                    fmaxf(c[mt][2 * kt][1], 0.f));
            af[mt][kt][1] = pack_h2(fmaxf(c[mt][2 * kt][2], 0.f),
                                    fmaxf(c[mt][2 * kt][3], 0.f));
            af[mt][kt][2] = pack_h2(fmaxf(c[mt][2 * kt + 1][0], 0.f),
                                    fmaxf(c[mt][2 * kt + 1][1], 0.f));
            af[mt][kt][3] = pack_h2(fmaxf(c[mt][2 * kt + 1][2], 0.f),
                                    fmaxf(c[mt][2 * kt + 1][3], 0.f));
        }
}

// init accumulators with bias (broadcast over rows).
__device__ __forceinline__ void c_init(float c[2][12][4],
                                       const float2* __restrict__ bf, int tig) {
#pragma unroll
    for (int nt = 0; nt < 12; nt++) {
        const float2 f = bf[nt * 4 + tig];
#pragma unroll
        for (int mt = 0; mt < 2; mt++) {
            c[mt][nt][0] = f.x; c[mt][nt][1] = f.y;
            c[mt][nt][2] = f.x; c[mt][nt][3] = f.y;
        }
    }
}

__global__ void __launch_bounds__(NT, 2)
mlp_regchain_kernel(const float* __restrict__ x, const float* __restrict__ ac,
                    const float* __restrict__ W0, const float* __restrict__ b0,
                    const float* __restrict__ W1, const float* __restrict__ b1,
                    const float* __restrict__ W2, const float* __restrict__ b2,
                    const float* __restrict__ W3, const float* __restrict__ b3,
                    float* __restrict__ out) {
    __shared__ SMem sm;
    const int tid  = threadIdx.x;
    const int w    = tid >> 5;
    const int lane = tid & 31;
    const int gid  = lane >> 2;
    const int tig  = lane & 3;

    // ---- stage W1/W2 B-fragments (fp16) ----
    for (int i = tid; i < 4608; i += NT) {
        const int g8 = i >> 4;             // (kt*6+ntp)*8 + gid'
        const int sg = g8 & 7;
        const int kp = g8 >> 3;            // kt*6+ntp
        const int kt = kp / 6, ntp = kp - kt * 6;
        const int tg = (i >> 2) & 3, q = i & 3;
        const int nt = 2 * ntp + (q >> 1);
        const int k0 = kt * 16 + ((q & 1) ? 8 : 0) + 2 * tg;
        const int n  = nt * 8 + sg;
        const bool okn = (n < 90);
        float v0 = (k0 < 90 && okn) ? W1[k0 * 90 + n] : 0.f;
        float v1 = (k0 + 1 < 90 && okn) ? W1[(k0 + 1) * 90 + n] : 0.f;
        sm.w1f[i] = pack_h2(v0, v1);
        v0 = (k0 < 90 && okn) ? W2[k0 * 90 + n] : 0.f;
        v1 = (k0 + 1 < 90 && okn) ? W2[(k0 + 1) * 90 + n] : 0.f;
        sm.w2f[i] = pack_h2(v0, v1);
    }
    if (tid < 48) {
        const int nt = tid >> 2, tg = tid & 3;
        const int n0 = nt * 8 + 2 * tg;
        const float z0 = (n0 < 90) ? 1.f : 0.f, z1 = (n0 + 1 < 90) ? 1.f : 0.f;
        sm.b0f[tid] = make_float2(z0 ? ((n0 < 90) ? b0[n0] : 0.f) : 0.f,
                                  z1 ? b0[n0 + 1] : 0.f);
        sm.b1f[tid] = make_float2((n0 < 90) ? b1[n0] : 0.f,
                                  (n0 + 1 < 90) ? b1[n0 + 1] : 0.f);
        sm.b2f[tid] = make_float2((n0 < 90) ? b2[n0] : 0.f,
                                  (n0 + 1 < 90) ? b2[n0 + 1] : 0.f);
        sm.w3f[tid] = make_float2((n0 < 90) ? W3[n0] : 0.f,
                                  (n0 + 1 < 90) ? W3[n0 + 1] : 0.f);
    }
    if (tid < 60) sm.cs[tid] = ac[tid];

    // ---- layer-1 W0 B-fragments in registers (constant all kernel) ----
    uint32_t w0b[12];
#pragma unroll
    for (int nt = 0; nt < 12; nt++) {
        const int n = nt * 8 + gid;
        const int e0 = 2 * tig, e1 = 2 * tig + 1;
        const float v0 = (e0 < 7 && n < 90) ? W0[e0 * 90 + n] : 0.f;
        const float v1 = (e1 < 7 && n < 90) ? W0[e1 * 90 + n] : 0.f;
        w0b[nt] = pack_h2(v0, v1);
    }
    const float b3v = b3[0];
    __syncthreads();

    // ---- main loop: no barriers, warps fully independent ----
    for (int ct = blockIdx.x; ct < NCTILES; ct += gridDim.x) {
        const int R = ct * CTILE + w * 32;

        // layer-1 inputs: gather electrodes, fp16 hi/lo split
        uint32_t ah[4], al[4];
#pragma unroll
        for (int m = 0; m < 4; m++) {
            const int r = R + gid + 8 * m;
            const int g = r / LL, l = r - g * LL;
            const int b = g / 30, rem = g - b * 30;
            const int dev = rem % 5;
            const int i = l / 60, j = l - i * 60;
            const float* xb = x + (b * 64 + i + dev) * 64 + j;
            float va, vb;
            if (tig == 0)      { va = xb[1]; vb = xb[2]; }
            else if (tig == 1) { va = xb[3]; vb = xb[4]; }
            else if (tig == 2) { va = sm.cs[rem * 2]; vb = xb[0]; }
            else               { va = sm.cs[rem * 2 + 1]; vb = 0.f; }
            const __half ha = __float2half_rn(va), hb = __float2half_rn(vb);
            const __half2 hh = __halves2half2(ha, hb);
            ah[m] = *(const uint32_t*)&hh;
            al[m] = pack_h2(va - __half2float(ha), vb - __half2float(hb));
        }
        uint32_t af[2][6][4];
        const uint32_t A0[4] = {ah[0], ah[1], al[0], al[1]};
        const uint32_t A1[4] = {ah[2], ah[3], al[2], al[3]};

        float c[2][12][4];

        // layer 1: K=16 (hi electrodes | lo residual vs duplicated W0)
        c_init(c, sm.b0f, tig);
#pragma unroll
        for (int nt = 0; nt < 12; nt++) {
            mma16(c[0][nt], A0, w0b[nt], w0b[nt]);
            mma16(c[1][nt], A1, w0b[nt], w0b[nt]);
        }
        c_to_a(c, af);

        // layer 2
        c_init(c, sm.b1f, tig);
        gemmw(sm.w1f, af, c, gid, tig);
        c_to_a(c, af);

        // layer 3
        c_init(c, sm.b2f, tig);
        gemmw(sm.w2f, af, c, gid, tig);

        // final: relu + dot(W3) + reduce over tig + atomic out
#pragma unroll
        for (int mt = 0; mt < 2; mt++) {
            float s0 = 0.f, s1 = 0.f;
#pragma unroll
            for (int nt = 0; nt < 12; nt++) {
                const float2 wq = sm.w3f[nt * 4 + tig];
                s0 = fmaf(fmaxf(c[mt][nt][0], 0.f), wq.x, s0);
                s0 = fmaf(fmaxf(c[mt][nt][1], 0.f), wq.y, s0);
                s1 = fmaf(fmaxf(c[mt][nt][2], 0.f), wq.x, s1);
                s1 = fmaf(fmaxf(c[mt][nt][3], 0.f), wq.y, s1);
            }
            s0 += __shfl_xor_sync(0xffffffffu, s0, 1);
            s0 += __shfl_xor_sync(0xffffffffu, s0, 2);
            s1 += __shfl_xor_sync(0xffffffffu, s1, 1);
            s1 += __shfl_xor_sync(0xffffffffu, s1, 2);
            if (tig == 0) {
                int r0 = R + gid + 16 * mt;
                int g = r0 / LL, l = r0 - g * LL;
                int b = g / 30, rem = g - b * 30;
                int oc = rem / 5;
                atomicAdd(out + (b * OC + oc) * LL + l, s0 + b3v);
                const int r1 = r0 + 8;
                g = r1 / LL; l = r1 - g * LL;
                b = g / 30; rem = g - b * 30; oc = rem / 5;
                atomicAdd(out + (b * OC + oc) * LL + l, s1 + b3v);
            }
        }
    }
}

__global__ void zero_kernel(float* o, int n) {
    int i = blockIdx.x * blockDim.x + threadIdx.x;
    if (i < n) o[i] = 0.f;
}

extern "C" void kernel_launch(void* const* d_in, const int* in_sizes, int n_in,
                              void* d_out, int out_size) {
    const float* x  = (const float*)d_in[0];
    const float* ac = (const float*)d_in[1];
    const float* W0 = (const float*)d_in[2];
    const float* b0 = (const float*)d_in[3];
    const float* W1 = (const float*)d_in[4];
    const float* b1 = (const float*)d_in[5];
    const float* W2 = (const float*)d_in[6];
    const float* b2 = (const float*)d_in[7];
    const float* W3 = (const float*)d_in[8];
    const float* b3 = (const float*)d_in[9];
    float* out = (float*)d_out;

    int sms = 0;
    cudaDeviceGetAttribute(&sms, cudaDevAttrMultiProcessorCount, 0);
    if (sms <= 0) sms = 148;
    int grid = 2 * sms;
    if (grid > NCTILES) grid = NCTILES;

    zero_kernel<<<(NROWS / 5 + 255) / 256, 256>>>(out, NROWS / 5);
    mlp_regchain_kernel<<<grid, NT>>>(x, ac, W0, b0, W1, b1, W2, b2, W3, b3, out);
}

// round 7
// speedup vs baseline: 9.2574x; 1.0452x over previous
#include <cuda_runtime.h>
#include <cuda_fp16.h>
#include <cstdint>

// ---------------- problem constants ----------------
#define OC 6
#define LL 3600
#define NROWS 864000
#define NT 256
#define CTILE 128                 // 8 warps x 16 rows
#define NCTILES (NROWS / CTILE)   // 6750

__device__ __forceinline__ uint32_t pack_h2(float a, float b) {
    __half2 h = __floats2half2_rn(a, b);
    return *(uint32_t*)&h;
}

__device__ __forceinline__ void mma16(float c[4], const uint32_t a[4],
                                      uint32_t b0, uint32_t b1) {
    asm volatile(
        "mma.sync.aligned.m16n8k16.row.col.f32.f16.f16.f32 "
        "{%0,%1,%2,%3}, {%4,%5,%6,%7}, {%8,%9}, {%0,%1,%2,%3};"
        : "+f"(c[0]), "+f"(c[1]), "+f"(c[2]), "+f"(c[3])
        : "r"(a[0]), "r"(a[1]), "r"(a[2]), "r"(a[3]), "r"(b0), "r"(b1));
}

// B-frag SMEM layout: word idx = ((kt*6+ntp)*8+gid)*16 + tig*4 + q
//   q0 = b0 of nt=2ntp, q1 = b1 of nt=2ntp, q2 = b0 of nt=2ntp+1, q3 = b1.
// One LDS.128 per (kt,ntp) per thread; conflict-free.
struct SMem {
    uint32_t w1f[4608];
    uint32_t w2f[4608];
    float2 b0f[48], b1f[48], b2f[48], w3f[48];
    float cs[64];
};

// 16x96 += 16x96(A) @ 96x96(W): 6 K-blocks, 12 n-tiles.
__device__ __forceinline__ void gemmw(const uint32_t* __restrict__ wf,
                                      const uint32_t af[6][4],
                                      float c[12][4], int gid, int tig) {
#pragma unroll
    for (int kt = 0; kt < 6; kt++) {
#pragma unroll
        for (int ntp = 0; ntp < 6; ntp++) {
            const uint4 bv =
                *(const uint4*)(wf + ((kt * 6 + ntp) * 8 + gid) * 16 + tig * 4);
            mma16(c[2 * ntp],     af[kt], bv.x, bv.y);
            mma16(c[2 * ntp + 1], af[kt], bv.z, bv.w);
        }
    }
}

// relu + fp16-pack C fragments into next layer's A fragments (registers only).
__device__ __forceinline__ void c_to_a(const float c[12][4], uint32_t af[6][4]) {
#pragma unroll
    for (int kt = 0; kt < 6; kt++) {
        af[kt][0] = pack_h2(fmaxf(c[2 * kt][0], 0.f), fmaxf(c[2 * kt][1], 0.f));
        af[kt][1] = pack_h2(fmaxf(c[2 * kt][2], 0.f), fmaxf(c[2 * kt][3], 0.f));
        af[kt][2] = pack_h2(fmaxf(c[2 * kt + 1][0], 0.f), fmaxf(c[2 * kt + 1][1], 0.f));
        af[kt][3] = pack_h2(fmaxf(c[2 * kt + 1][2], 0.f), fmaxf(c[2 * kt + 1][3], 0.f));
    }
}

__device__ __forceinline__ void c_init(float c[12][4],
                                       const float2* __restrict__ bf, int tig) {
#pragma unroll
    for (int nt = 0; nt < 12; nt++) {
        const float2 f = bf[nt * 4 + tig];
        c[nt][0] = f.x; c[nt][1] = f.y; c[nt][2] = f.x; c[nt][3] = f.y;
    }
}

__global__ void __launch_bounds__(NT, 2)
mlp_regchain2_kernel(const float* __restrict__ x, const float* __restrict__ ac,
                     const float* __restrict__ W0, const float* __restrict__ b0,
                     const float* __restrict__ W1, const float* __restrict__ b1,
                     const float* __restrict__ W2, const float* __restrict__ b2,
                     const float* __restrict__ W3, const float* __restrict__ b3,
                     float* __restrict__ out) {
    __shared__ SMem sm;
    const int tid  = threadIdx.x;
    const int w    = tid >> 5;
    const int lane = tid & 31;
    const int gid  = lane >> 2;
    const int tig  = lane & 3;

    // ---- stage W1/W2 B-fragments (fp16) ----
    for (int i = tid; i < 4608; i += NT) {
        const int g8 = i >> 4;
        const int sg = g8 & 7;
        const int kp = g8 >> 3;            // kt*6+ntp
        const int kt = kp / 6, ntp = kp - kt * 6;
        const int tg = (i >> 2) & 3, q = i & 3;
        const int nt = 2 * ntp + (q >> 1);
        const int k0 = kt * 16 + ((q & 1) ? 8 : 0) + 2 * tg;
        const int n  = nt * 8 + sg;
        const bool okn = (n < 90);
        float v0 = (k0 < 90 && okn) ? W1[k0 * 90 + n] : 0.f;
        float v1 = (k0 + 1 < 90 && okn) ? W1[(k0 + 1) * 90 + n] : 0.f;
        sm.w1f[i] = pack_h2(v0, v1);
        v0 = (k0 < 90 && okn) ? W2[k0 * 90 + n] : 0.f;
        v1 = (k0 + 1 < 90 && okn) ? W2[(k0 + 1) * 90 + n] : 0.f;
        sm.w2f[i] = pack_h2(v0, v1);
    }
    if (tid < 48) {
        const int nt = tid >> 2, tg = tid & 3;
        const int n0 = nt * 8 + 2 * tg;
        sm.b0f[tid] = make_float2((n0 < 90) ? b0[n0] : 0.f,
                                  (n0 + 1 < 90) ? b0[n0 + 1] : 0.f);
        sm.b1f[tid] = make_float2((n0 < 90) ? b1[n0] : 0.f,
                                  (n0 + 1 < 90) ? b1[n0 + 1] : 0.f);
        sm.b2f[tid] = make_float2((n0 < 90) ? b2[n0] : 0.f,
                                  (n0 + 1 < 90) ? b2[n0 + 1] : 0.f);
        sm.w3f[tid] = make_float2((n0 < 90) ? W3[n0] : 0.f,
                                  (n0 + 1 < 90) ? W3[n0 + 1] : 0.f);
    }
    if (tid < 60) sm.cs[tid] = ac[tid];

    // ---- W0 B-fragments in registers ----
    uint32_t w0b[12];
#pragma unroll
    for (int nt = 0; nt < 12; nt++) {
        const int n = nt * 8 + gid;
        const int e0 = 2 * tig, e1 = 2 * tig + 1;
        const float v0 = (e0 < 7 && n < 90) ? W0[e0 * 90 + n] : 0.f;
        const float v1 = (e1 < 7 && n < 90) ? W0[e1 * 90 + n] : 0.f;
        w0b[nt] = pack_h2(v0, v1);
    }
    const float b3v = b3[0];
    __syncthreads();

    // ---- main loop: no barriers, warps fully independent ----
    for (int ct = blockIdx.x; ct < NCTILES; ct += gridDim.x) {
        const int R = ct * CTILE + w * 16;

        // layer-1 inputs for rows R+gid, R+gid+8: hi/lo fp16 split
        uint32_t A0[4];
#pragma unroll
        for (int m = 0; m < 2; m++) {
            const int r = R + gid + 8 * m;
            const int g = r / LL, l = r - g * LL;
            const int b = g / 30, rem = g - b * 30;
            const int dev = rem % 5;
            const int i = l / 60, j = l - i * 60;
            const float* xb = x + (b * 64 + i + dev) * 64 + j;
            float va, vb;
            if (tig == 0)      { va = xb[1]; vb = xb[2]; }
            else if (tig == 1) { va = xb[3]; vb = xb[4]; }
            else if (tig == 2) { va = sm.cs[rem * 2]; vb = xb[0]; }
            else               { va = sm.cs[rem * 2 + 1]; vb = 0.f; }
            const __half ha = __float2half_rn(va), hb = __float2half_rn(vb);
            const __half2 hh = __halves2half2(ha, hb);
            A0[m]     = *(const uint32_t*)&hh;                     // hi halves
            A0[m + 2] = pack_h2(va - __half2float(ha), vb - __half2float(hb));
        }

        float c[12][4];
        uint32_t af[6][4];

        // layer 1: one K=16 MMA per n-tile (hi | lo residual, W0 duplicated)
        c_init(c, sm.b0f, tig);
#pragma unroll
        for (int nt = 0; nt < 12; nt++) mma16(c[nt], A0, w0b[nt], w0b[nt]);
        c_to_a(c, af);

        // layer 2
        c_init(c, sm.b1f, tig);
        gemmw(sm.w1f, af, c, gid, tig);
        c_to_a(c, af);

        // layer 3
        c_init(c, sm.b2f, tig);
        gemmw(sm.w2f, af, c, gid, tig);

        // final: relu + dot(W3) + tig-reduce + atomic out
        float s0 = 0.f, s1 = 0.f;
#pragma unroll
        for (int nt = 0; nt < 12; nt++) {
            const float2 wq = sm.w3f[nt * 4 + tig];
            s0 = fmaf(fmaxf(c[nt][0], 0.f), wq.x, s0);
            s0 = fmaf(fmaxf(c[nt][1], 0.f), wq.y, s0);
            s1 = fmaf(fmaxf(c[nt][2], 0.f), wq.x, s1);
            s1 = fmaf(fmaxf(c[nt][3], 0.f), wq.y, s1);
        }
        s0 += __shfl_xor_sync(0xffffffffu, s0, 1);
        s0 += __shfl_xor_sync(0xffffffffu, s0, 2);
        s1 += __shfl_xor_sync(0xffffffffu, s1, 1);
        s1 += __shfl_xor_sync(0xffffffffu, s1, 2);
        if (tig == 0) {
            int r0 = R + gid;
            int g = r0 / LL, l = r0 - g * LL;
            int b = g / 30, rem = g - b * 30;
            int oc = rem / 5;
            atomicAdd(out + (b * OC + oc) * LL + l, s0 + b3v);
            const int r1 = r0 + 8;
            g = r1 / LL; l = r1 - g * LL;
            b = g / 30; rem = g - b * 30; oc = rem / 5;
            atomicAdd(out + (b * OC + oc) * LL + l, s1 + b3v);
        }
    }
}

__global__ void zero_kernel(float* o, int n) {
    int i = blockIdx.x * blockDim.x + threadIdx.x;
    if (i < n) o[i] = 0.f;
}

extern "C" void kernel_launch(void* const* d_in, const int* in_sizes, int n_in,
                              void* d_out, int out_size) {
    const float* x  = (const float*)d_in[0];
    const float* ac = (const float*)d_in[1];
    const float* W0 = (const float*)d_in[2];
    const float* b0 = (const float*)d_in[3];
    const float* W1 = (const float*)d_in[4];
    const float* b1 = (const float*)d_in[5];
    const float* W2 = (const float*)d_in[6];
    const float* b2 = (const float*)d_in[7];
    const float* W3 = (const float*)d_in[8];
    const float* b3 = (const float*)d_in[9];
    float* out = (float*)d_out;

    int sms = 0;
    cudaDeviceGetAttribute(&sms, cudaDevAttrMultiProcessorCount, 0);
    if (sms <= 0) sms = 148;
    int grid = 2 * sms;
    if (grid > NCTILES) grid = NCTILES;

    zero_kernel<<<(NROWS / 5 + 255) / 256, 256>>>(out, NROWS / 5);
    mlp_regchain2_kernel<<<grid, NT>>>(x, ac, W0, b0, W1, b1, W2, b2, W3, b3, out);
}